// round 14
// baseline (speedup 1.0000x reference)
#include <cuda_runtime.h>
#include <cuda_bf16.h>
#include <cstdint>

#define T_DIM 8192
#define K_DIM 2048
#define TM1   (T_DIM - 1)                      // 8191 rows in the loss
#define NTOT  ((long long)TM1 * K_DIM)         // 16,775,168 elements
#define NVEC  (NTOT / 4)                       // 4,193,792 float4
#define GAMMA 0.99f
#define LOGG  (-0.0100503358535014f)           // logf(0.99)

#define SCAN_BLOCKS  256                       // FIRST block IDs -> spread over all SMs
#define NBLOCKS      1184                      // 8 blocks/SM * 148 SMs
#define NSLICE       1024                      // 1024 slices x 4096 float4 (64 KB each)
#define NPART        (NSLICE + SCAN_BLOCKS)
#define FULLM        0xFFFFFFFFu

#define RPAD   68                              // rows-per-col stride (64+4): conflict-free
#define NRND   128                             // 128 rounds x 64 rows >= TM1

// Scratch (device globals are the allowed scratch mechanism).
__device__ float2       g_dp  [(long long)K_DIM * TM1];  // {decay, td*decay}, [k][t]
__device__ double       g_part[NPART];
__device__ unsigned int g_work;                          // slice ticket; self-resetting
__device__ unsigned int g_done;                          // block ticket; self-resetting

__device__ __forceinline__ float sl1(float pred, float target) {
    float a = fabsf(pred - target);
    float m = fminf(a, 1.0f);
    return m * (a - 0.5f * m);
}
__device__ __forceinline__ float sl1_acc(float acc, float d) {
    float a = fabsf(d);
    float m = fminf(a, 1.0f);
    return fmaf(m, fmaf(-0.5f, m, a), acc);
}

__device__ __forceinline__ unsigned int smem_u32(const void* p) {
    return (unsigned int)__cvta_generic_to_shared(p);
}
// L2 evict-last policy: keep the replayed working set resident in the 126MB L2.
__device__ __forceinline__ unsigned long long mk_policy() {
    unsigned long long pol;
    asm("createpolicy.fractional.L2::evict_last.b64 %0, 1.0;" : "=l"(pol));
    return pol;
}
__device__ __forceinline__ void cpa4(unsigned int dst, const float* src,
                                     unsigned long long pol) {
    asm volatile("cp.async.ca.shared.global.L2::cache_hint [%0], [%1], 4, %2;"
                 :: "r"(dst), "l"(src), "l"(pol));
}
__device__ __forceinline__ float4 ldg_el(const float4* p, unsigned long long pol) {
    float4 v;
    asm volatile("ld.global.nc.L2::cache_hint.v4.f32 {%0,%1,%2,%3}, [%4], %5;"
                 : "=f"(v.x), "=f"(v.y), "=f"(v.z), "=f"(v.w)
                 : "l"(p), "l"(pol));
    return v;
}
__device__ __forceinline__ void stg_dp_el(float2* p, float x, float y,
                                          unsigned long long pol) {
    asm volatile("st.global.L2::cache_hint.v2.f32 [%0], {%1,%2}, %3;"
                 :: "l"(p), "f"(x), "f"(y), "l"(pol) : "memory");
}
#define CPC()  asm volatile("cp.async.commit_group;")
#define CPW(n) asm volatile("cp.async.wait_group %0;" :: "n"(n))

__global__ void __launch_bounds__(256, 8)
retrace_main(const float* __restrict__ q,
             const float* __restrict__ tq,
             const float* __restrict__ tv,
             const float* __restrict__ r,
             const float* __restrict__ olp,
             const float* __restrict__ tlp,
             float* __restrict__ out)
{
    const int tid  = threadIdx.x;
    const int lane = tid & 31;
    const int wrp  = tid >> 5;
    const unsigned long long pol = mk_policy();

    __shared__ float s_liw[2][8 * RPAD];    // forward: tlp ; backward: q tile
    __shared__ float s_r  [2][8 * RPAD];    // forward: r   ; backward: dp.x plane
    __shared__ float s_tv [2][8 * RPAD];    // forward: tv  ; backward: dp.y plane
    __shared__ float s_tq [2][8 * RPAD];
    __shared__ int    s_nch[8];
    __shared__ double shw[8];
    __shared__ int    s_v;

    auto block_reduce = [&](double val) -> double {   // deterministic fixed order
        #pragma unroll
        for (int off = 16; off > 0; off >>= 1)
            val += __shfl_xor_sync(FULLM, val, off);
        __syncthreads();
        if (lane == 0) shw[wrp] = val;
        __syncthreads();
        double s = 0.0;
        #pragma unroll
        for (int i = 0; i < 8; ++i) s += shw[i];
        return s;
    };

    if (blockIdx.x < SCAN_BLOCKS) {
        // ===== one WARP per column; 64-row rounds staged via cp.async, 2-deep =====
        const int k0 = blockIdx.x * 8;
        const int k  = k0 + wrp;
        double acc = 0.0;

        float carry = 0.0f;
        int   tstop = TM1;
        bool  warp_dead = false;

        auto stage_f = [&](int buf, int rnd) {
            #pragma unroll
            for (int i = 0; i < 2; ++i) {
                const int idx = tid + 256 * i;
                const int row = idx >> 3, col = idx & 7;
                const int tc  = min(rnd * 64 + row, TM1 - 1);
                const unsigned int d = (unsigned int)(col * RPAD + row) * 4u;
                cpa4(smem_u32(&s_liw[buf][0]) + d, tlp + (size_t)(tc + 1) * K_DIM + k0 + col, pol);
                cpa4(smem_u32(&s_r  [buf][0]) + d, r   + (size_t)tc       * K_DIM + k0 + col, pol);
                cpa4(smem_u32(&s_tv [buf][0]) + d, tv  + (size_t)(tc + 1) * K_DIM + k0 + col, pol);
                cpa4(smem_u32(&s_tq [buf][0]) + d, tq  + (size_t)(tc + 1) * K_DIM + k0 + col, pol);
            }
        };
        auto comp_sub = [&](int buf, int rnd, int s) {
            const int  sc = rnd * 2 + s;
            const int  t  = sc * 32 + lane;
            const bool v  = t < TM1;
            const int  ro = s * 32 + lane;
            float liw = s_liw[buf][wrp * RPAD + ro] - (v ? olp[t + 1] : 0.0f);
            float m   = fminf(liw, 0.0f);
            float iw  = expf(m);
            float sv  = v ? (LOGG + m) : 0.0f;
            #pragma unroll
            for (int off = 1; off < 32; off <<= 1) {     // inclusive prefix sum
                float u = __shfl_up_sync(FULLM, sv, off);
                if (lane >= off) sv += u;
            }
            float ls    = carry + sv;
            float decay = expf(ls);                       // underflows to exact 0
            float pdv   = (s_r[buf][wrp * RPAD + ro]
                           + GAMMA * (s_tv[buf][wrp * RPAD + ro]
                                      - iw * s_tq[buf][wrp * RPAD + ro])) * decay;
            if (v) stg_dp_el(&g_dp[(size_t)k * TM1 + t], decay, pdv, pol);
            carry = __shfl_sync(FULLM, ls, 31);
            unsigned bal = __ballot_sync(FULLM, v && decay == 0.0f);
            if (bal && !warp_dead) { tstop = sc * 32 + (__ffs(bal) - 1); warp_dead = true; }
        };

        stage_f(0, 0); CPC();
        stage_f(1, 1); CPC();
        int rnd = 0;
        while (true) {
            CPW(1);
            __syncthreads();
            const int buf = rnd & 1;
            if (!warp_dead) comp_sub(buf, rnd, 0);
            if (!warp_dead) comp_sub(buf, rnd, 1);
            const bool allstop = __syncthreads_and(warp_dead) != 0;
            if (allstop || rnd + 1 >= NRND) break;
            if (rnd + 2 < NRND) stage_f(buf, rnd + 2);
            CPC();
            ++rnd;
        }

        const int nch = (tstop + 31) >> 5;
        if (lane == 0) s_nch[wrp] = nch;
        __syncthreads();
        int bmax = s_nch[0];
        #pragma unroll
        for (int i = 1; i < 8; ++i) bmax = max(bmax, s_nch[i]);
        const int rmax = (bmax + 1) >> 1;

        // ---- backward: q and dp tiles staged via cp.async ----
        auto stage_b = [&](int buf, int rr) {
            #pragma unroll
            for (int i = 0; i < 2; ++i) {
                const int idx = tid + 256 * i;
                const int row = idx >> 3, col = idx & 7;
                const int tc  = min(rr * 64 + row, TM1 - 1);
                const unsigned int d = (unsigned int)(col * RPAD + row) * 4u;
                const float* dpp = (const float*)&g_dp[(size_t)(k0 + col) * TM1 + tc];
                cpa4(smem_u32(&s_liw[buf][0]) + d, q + (size_t)tc * K_DIM + k0 + col, pol);
                cpa4(smem_u32(&s_r  [buf][0]) + d, dpp, pol);       // dp.x plane
                cpa4(smem_u32(&s_tv [buf][0]) + d, dpp + 1, pol);   // dp.y plane
            }
        };

        CPW(0);
        __syncthreads();
        float Rcarry = 0.0f;
        stage_b((rmax - 1) & 1, rmax - 1); CPC();
        for (int rr = rmax - 1; ; --rr) {
            if (rr > 0) { stage_b((rr - 1) & 1, rr - 1); CPC(); CPW(1); }
            else        { CPW(0); }
            __syncthreads();
            const int buf = rr & 1;
            #pragma unroll
            for (int s2 = 1; s2 >= 0; --s2) {
                const int  sc = 2 * rr + s2;
                const int  t  = sc * 32 + lane;
                const bool v  = (sc < nch) && (t < TM1);
                const int  ro = s2 * 32 + lane;
                float s = s_tv[buf][wrp * RPAD + ro];
                #pragma unroll
                for (int off = 1; off < 32; off <<= 1) {
                    float u = __shfl_down_sync(FULLM, s, off);
                    if (lane + off < 32) s += u;
                }
                float R    = s + Rcarry;
                float retr = R / fmaxf(s_r[buf][wrp * RPAD + ro], 1e-10f);
                float qv   = s_liw[buf][wrp * RPAD + ro];
                if (v) acc += (double)(sl1(qv, retr) - sl1(qv, 0.0f));
                Rcarry = __shfl_sync(FULLM, R, 0);
            }
            if (rr == 0) break;
            __syncthreads();
        }

        double bsum = block_reduce(acc);
        if (tid == 0) g_part[NSLICE + blockIdx.x] = bsum;
    }

    // ===== dynamic work-stealing over 1024 contiguous qsum slices =====
    // g_part[v] is slice-indexed -> value and finalize order deterministic
    // regardless of which block computes which slice.
    const float4* q4 = (const float4*)q;
    while (true) {
        if (tid == 0) s_v = (int)atomicAdd(&g_work, 1u);
        __syncthreads();
        const int v = s_v;
        if (v >= NSLICE) break;

        const long long base = (long long)v * 4096 + tid;
        float f0 = 0.0f, f1 = 0.0f, f2 = 0.0f, f3 = 0.0f;
        #pragma unroll
        for (int b = 0; b < 4; ++b) {
            const long long i0 = base + 1024 * b;
            float4 a = make_float4(0.f, 0.f, 0.f, 0.f);
            float4 c = a, d2 = a, e = a;
            if (i0        < NVEC) a  = ldg_el(q4 + i0,       pol);
            if (i0 + 256  < NVEC) c  = ldg_el(q4 + i0 + 256, pol);
            if (i0 + 512  < NVEC) d2 = ldg_el(q4 + i0 + 512, pol);
            if (i0 + 768  < NVEC) e  = ldg_el(q4 + i0 + 768, pol);
            f0 = sl1_acc(sl1_acc(sl1_acc(sl1_acc(f0, a.x),  a.y),  a.z),  a.w);
            f1 = sl1_acc(sl1_acc(sl1_acc(sl1_acc(f1, c.x),  c.y),  c.z),  c.w);
            f2 = sl1_acc(sl1_acc(sl1_acc(sl1_acc(f2, d2.x), d2.y), d2.z), d2.w);
            f3 = sl1_acc(sl1_acc(sl1_acc(sl1_acc(f3, e.x),  e.y),  e.z),  e.w);
        }
        double ssum = block_reduce((double)((f0 + f1) + (f2 + f3)));
        if (tid == 0) g_part[v] = ssum;
        __syncthreads();                     // protect s_v / shw for next iteration
    }

    // ---- fused last-block finalize (deterministic fixed-order final sum) ----
    __shared__ unsigned int sticket;
    if (tid == 0) {
        __threadfence();
        sticket = atomicAdd(&g_done, 1u);
    }
    __syncthreads();
    if (sticket == NBLOCKS - 1) {
        __threadfence();
        double a = 0.0;
        for (int i = tid; i < NPART; i += 256) a += g_part[i];
        __shared__ double sh[256];
        sh[tid] = a;
        __syncthreads();
        #pragma unroll
        for (int s = 128; s > 0; s >>= 1) {
            if (tid < s) sh[tid] += sh[tid + s];
            __syncthreads();
        }
        if (tid == 0) {
            out[0] = (float)(sh[0] / (double)NTOT);
            g_work = 0;                      // reset tickets for next graph replay
            g_done = 0;
        }
    }
}

extern "C" void kernel_launch(void* const* d_in, const int* in_sizes, int n_in,
                              void* d_out, int out_size)
{
    const float* q   = (const float*)d_in[0];  // state_trajectory_action_values (T,K)
    const float* tq  = (const float*)d_in[1];  // target_state_trajectory_action_values (T,K)
    const float* tv  = (const float*)d_in[2];  // target_expected_state_values (T,K)
    const float* r   = (const float*)d_in[3];  // rewards (T,K)
    const float* olp = (const float*)d_in[4];  // original_log_trajectory_action_probs (T,)
    const float* tlp = (const float*)d_in[5];  // target_log_trajectory_task_action_probs (T,K)
    float* out = (float*)d_out;

    retrace_main<<<NBLOCKS, 256>>>(q, tq, tv, r, olp, tlp, out);
}

// round 15
// speedup vs baseline: 1.1003x; 1.1003x over previous
#include <cuda_runtime.h>
#include <cuda_bf16.h>
#include <cstdint>

#define T_DIM 8192
#define K_DIM 2048
#define TM1   (T_DIM - 1)                      // 8191 rows in the loss
#define NTOT  ((long long)TM1 * K_DIM)         // 16,775,168 elements
#define NVEC  (NTOT / 4)                       // 4,193,792 float4
#define GAMMA 0.99f
#define LOGG  (-0.0100503358535014f)           // logf(0.99)

#define SCAN_BLOCKS  256                       // FIRST block IDs -> spread over all SMs
#define NBLOCKS      592                       // 4 blocks/SM * 148 SMs (one wave, 64 regs)
#define NSLICE       512                       // 512 slices x 8192 float4 (128 KB each)
#define NPART        (NSLICE + SCAN_BLOCKS)
#define FULLM        0xFFFFFFFFu

#define RPAD   68                              // rows-per-col stride (64+4): conflict-free
#define NRND   128                             // 128 rounds x 64 rows >= TM1

// Scratch (device globals are the allowed scratch mechanism).
__device__ float2       g_dp  [(long long)K_DIM * TM1];  // {decay, td*decay}, [k][t]
__device__ double       g_part[NPART];
__device__ unsigned int g_work;                          // slice ticket; self-resetting
__device__ unsigned int g_done;                          // block ticket; self-resetting

__device__ __forceinline__ float sl1(float pred, float target) {
    float a = fabsf(pred - target);
    float m = fminf(a, 1.0f);
    return m * (a - 0.5f * m);
}
__device__ __forceinline__ float sl1_acc(float acc, float d) {
    float a = fabsf(d);
    float m = fminf(a, 1.0f);
    return fmaf(m, fmaf(-0.5f, m, a), acc);
}

__device__ __forceinline__ unsigned int smem_u32(const void* p) {
    return (unsigned int)__cvta_generic_to_shared(p);
}
__device__ __forceinline__ void cpa4(unsigned int dst, const float* src) {
    asm volatile("cp.async.ca.shared.global [%0], [%1], 4;" :: "r"(dst), "l"(src));
}
#define CPC()  asm volatile("cp.async.commit_group;")
#define CPW(n) asm volatile("cp.async.wait_group %0;" :: "n"(n))

__global__ void __launch_bounds__(256, 4)
retrace_main(const float* __restrict__ q,
             const float* __restrict__ tq,
             const float* __restrict__ tv,
             const float* __restrict__ r,
             const float* __restrict__ olp,
             const float* __restrict__ tlp,
             float* __restrict__ out)
{
    const int tid  = threadIdx.x;
    const int lane = tid & 31;
    const int wrp  = tid >> 5;

    __shared__ float s_liw[2][8 * RPAD];    // forward: tlp ; backward: q tile
    __shared__ float s_r  [2][8 * RPAD];    // forward: r   ; backward: dp.x plane
    __shared__ float s_tv [2][8 * RPAD];    // forward: tv  ; backward: dp.y plane
    __shared__ float s_tq [2][8 * RPAD];
    __shared__ int    s_nch[8];
    __shared__ double shw[8];
    __shared__ int    s_v;

    auto block_reduce = [&](double val) -> double {   // deterministic fixed order
        #pragma unroll
        for (int off = 16; off > 0; off >>= 1)
            val += __shfl_xor_sync(FULLM, val, off);
        __syncthreads();
        if (lane == 0) shw[wrp] = val;
        __syncthreads();
        double s = 0.0;
        #pragma unroll
        for (int i = 0; i < 8; ++i) s += shw[i];
        return s;
    };

    if (blockIdx.x < SCAN_BLOCKS) {
        // ===== one WARP per column; 64-row rounds staged via cp.async, 2-deep =====
        const int k0 = blockIdx.x * 8;
        const int k  = k0 + wrp;
        double acc = 0.0;

        float carry = 0.0f;
        int   tstop = TM1;
        bool  warp_dead = false;

        auto stage_f = [&](int buf, int rnd) {
            #pragma unroll
            for (int i = 0; i < 2; ++i) {
                const int idx = tid + 256 * i;
                const int row = idx >> 3, col = idx & 7;
                const int tc  = min(rnd * 64 + row, TM1 - 1);
                const unsigned int d = (unsigned int)(col * RPAD + row) * 4u;
                cpa4(smem_u32(&s_liw[buf][0]) + d, tlp + (size_t)(tc + 1) * K_DIM + k0 + col);
                cpa4(smem_u32(&s_r  [buf][0]) + d, r   + (size_t)tc       * K_DIM + k0 + col);
                cpa4(smem_u32(&s_tv [buf][0]) + d, tv  + (size_t)(tc + 1) * K_DIM + k0 + col);
                cpa4(smem_u32(&s_tq [buf][0]) + d, tq  + (size_t)(tc + 1) * K_DIM + k0 + col);
            }
        };
        auto comp_sub = [&](int buf, int rnd, int s) {
            const int  sc = rnd * 2 + s;
            const int  t  = sc * 32 + lane;
            const bool v  = t < TM1;
            const int  ro = s * 32 + lane;
            float liw = s_liw[buf][wrp * RPAD + ro] - (v ? olp[t + 1] : 0.0f);
            float m   = fminf(liw, 0.0f);
            float iw  = expf(m);
            float sv  = v ? (LOGG + m) : 0.0f;
            #pragma unroll
            for (int off = 1; off < 32; off <<= 1) {     // inclusive prefix sum
                float u = __shfl_up_sync(FULLM, sv, off);
                if (lane >= off) sv += u;
            }
            float ls    = carry + sv;
            float decay = expf(ls);                       // underflows to exact 0
            float pdv   = (s_r[buf][wrp * RPAD + ro]
                           + GAMMA * (s_tv[buf][wrp * RPAD + ro]
                                      - iw * s_tq[buf][wrp * RPAD + ro])) * decay;
            if (v) g_dp[(size_t)k * TM1 + t] = make_float2(decay, pdv);
            carry = __shfl_sync(FULLM, ls, 31);
            unsigned bal = __ballot_sync(FULLM, v && decay == 0.0f);
            if (bal && !warp_dead) { tstop = sc * 32 + (__ffs(bal) - 1); warp_dead = true; }
        };

        stage_f(0, 0); CPC();
        stage_f(1, 1); CPC();
        int rnd = 0;
        while (true) {
            CPW(1);
            __syncthreads();
            const int buf = rnd & 1;
            if (!warp_dead) comp_sub(buf, rnd, 0);
            if (!warp_dead) comp_sub(buf, rnd, 1);
            const bool allstop = __syncthreads_and(warp_dead) != 0;
            if (allstop || rnd + 1 >= NRND) break;
            if (rnd + 2 < NRND) stage_f(buf, rnd + 2);
            CPC();
            ++rnd;
        }

        const int nch = (tstop + 31) >> 5;
        if (lane == 0) s_nch[wrp] = nch;
        __syncthreads();
        int bmax = s_nch[0];
        #pragma unroll
        for (int i = 1; i < 8; ++i) bmax = max(bmax, s_nch[i]);
        const int rmax = (bmax + 1) >> 1;

        // ---- backward: q and dp tiles staged via cp.async ----
        auto stage_b = [&](int buf, int rr) {
            #pragma unroll
            for (int i = 0; i < 2; ++i) {
                const int idx = tid + 256 * i;
                const int row = idx >> 3, col = idx & 7;
                const int tc  = min(rr * 64 + row, TM1 - 1);
                const unsigned int d = (unsigned int)(col * RPAD + row) * 4u;
                const float* dpp = (const float*)&g_dp[(size_t)(k0 + col) * TM1 + tc];
                cpa4(smem_u32(&s_liw[buf][0]) + d, q + (size_t)tc * K_DIM + k0 + col);
                cpa4(smem_u32(&s_r  [buf][0]) + d, dpp);       // dp.x plane
                cpa4(smem_u32(&s_tv [buf][0]) + d, dpp + 1);   // dp.y plane
            }
        };

        CPW(0);
        __syncthreads();
        float Rcarry = 0.0f;
        stage_b((rmax - 1) & 1, rmax - 1); CPC();
        for (int rr = rmax - 1; ; --rr) {
            if (rr > 0) { stage_b((rr - 1) & 1, rr - 1); CPC(); CPW(1); }
            else        { CPW(0); }
            __syncthreads();
            const int buf = rr & 1;
            #pragma unroll
            for (int s2 = 1; s2 >= 0; --s2) {
                const int  sc = 2 * rr + s2;
                const int  t  = sc * 32 + lane;
                const bool v  = (sc < nch) && (t < TM1);
                const int  ro = s2 * 32 + lane;
                float s = s_tv[buf][wrp * RPAD + ro];
                #pragma unroll
                for (int off = 1; off < 32; off <<= 1) {
                    float u = __shfl_down_sync(FULLM, s, off);
                    if (lane + off < 32) s += u;
                }
                float R    = s + Rcarry;
                float retr = R / fmaxf(s_r[buf][wrp * RPAD + ro], 1e-10f);
                float qv   = s_liw[buf][wrp * RPAD + ro];
                if (v) acc += (double)(sl1(qv, retr) - sl1(qv, 0.0f));
                Rcarry = __shfl_sync(FULLM, R, 0);
            }
            if (rr == 0) break;
            __syncthreads();
        }

        double bsum = block_reduce(acc);
        if (tid == 0) g_part[NSLICE + blockIdx.x] = bsum;
    }

    // ===== dynamic work-stealing over 512 x 128KB slices, 8 loads in flight =====
    // g_part[v] is slice-indexed -> value and finalize order deterministic
    // regardless of which block computes which slice.
    const float4* q4 = (const float4*)q;
    while (true) {
        if (tid == 0) s_v = (int)atomicAdd(&g_work, 1u);
        __syncthreads();
        const int v = s_v;
        if (v >= NSLICE) break;

        const long long base = (long long)v * 8192 + tid;   // 8192 float4 per slice
        float f0 = 0.0f, f1 = 0.0f, f2 = 0.0f, f3 = 0.0f;
        #pragma unroll
        for (int h = 0; h < 4; ++h) {                 // 4 batches x 8 float4/thread
            float4 x[8];
            #pragma unroll
            for (int j = 0; j < 8; ++j) {             // 8 independent loads in flight
                const long long i = base + (long long)h * 2048 + j * 256;
                x[j] = (i < NVEC) ? q4[i] : make_float4(0.f, 0.f, 0.f, 0.f);
            }
            #pragma unroll
            for (int j = 0; j < 8; ++j) {
                float4 a = x[j];
                float* f = (j & 2) ? ((j & 1) ? &f3 : &f2) : ((j & 1) ? &f1 : &f0);
                *f = sl1_acc(sl1_acc(sl1_acc(sl1_acc(*f, a.x), a.y), a.z), a.w);
            }
        }
        double ssum = block_reduce((double)((f0 + f1) + (f2 + f3)));
        if (tid == 0) g_part[v] = ssum;
        __syncthreads();                     // protect s_v / shw for next iteration
    }

    // ---- fused last-block finalize (deterministic fixed-order final sum) ----
    __shared__ unsigned int sticket;
    if (tid == 0) {
        __threadfence();
        sticket = atomicAdd(&g_done, 1u);
    }
    __syncthreads();
    if (sticket == NBLOCKS - 1) {
        __threadfence();
        double a = 0.0;
        for (int i = tid; i < NPART; i += 256) a += g_part[i];
        __shared__ double sh[256];
        sh[tid] = a;
        __syncthreads();
        #pragma unroll
        for (int s = 128; s > 0; s >>= 1) {
            if (tid < s) sh[tid] += sh[tid + s];
            __syncthreads();
        }
        if (tid == 0) {
            out[0] = (float)(sh[0] / (double)NTOT);
            g_work = 0;                      // reset tickets for next graph replay
            g_done = 0;
        }
    }
}

extern "C" void kernel_launch(void* const* d_in, const int* in_sizes, int n_in,
                              void* d_out, int out_size)
{
    const float* q   = (const float*)d_in[0];  // state_trajectory_action_values (T,K)
    const float* tq  = (const float*)d_in[1];  // target_state_trajectory_action_values (T,K)
    const float* tv  = (const float*)d_in[2];  // target_expected_state_values (T,K)
    const float* r   = (const float*)d_in[3];  // rewards (T,K)
    const float* olp = (const float*)d_in[4];  // original_log_trajectory_action_probs (T,)
    const float* tlp = (const float*)d_in[5];  // target_log_trajectory_task_action_probs (T,K)
    float* out = (float*)d_out;

    retrace_main<<<NBLOCKS, 256>>>(q, tq, tv, r, olp, tlp, out);
}

// round 16
// speedup vs baseline: 1.2083x; 1.0981x over previous
#include <cuda_runtime.h>
#include <cuda_bf16.h>
#include <cstdint>

#define T_DIM 8192
#define K_DIM 2048
#define TM1   (T_DIM - 1)                      // 8191 rows in the loss
#define NTOT  ((long long)TM1 * K_DIM)         // 16,775,168 elements
#define NVEC  (NTOT / 4)                       // 4,193,792 float4
#define GAMMA 0.99f
#define LOGG  (-0.0100503358535014f)           // logf(0.99)

#define SCAN_BLOCKS  256                       // FIRST block IDs -> spread over all SMs
#define NBLOCKS      592                       // 4 blocks/SM * 148 SMs (one wave)
#define NSLICE       512                       // 512 slices x 8192 float4 (128 KB each)
#define NPART        (NSLICE + SCAN_BLOCKS)
#define FULLM        0xFFFFFFFFu

#define RPAD     68                            // rows-per-col stride (64+4): conflict-free
#define NRND     128                           // 128 rounds x 64 rows >= TM1
#define DPROWS   320                           // smem-resident dp rows (10 sub-chunks)
#define DPSUB    (DPROWS / 32)                 // 10

// Scratch (device globals are the allowed scratch mechanism).
// g_dp is the rare-case spill for columns surviving >= DPROWS rows (zero-init).
__device__ float2       g_dp  [(long long)K_DIM * TM1];  // {decay, td*decay}, [k][t]
__device__ double       g_part[NPART];
__device__ unsigned int g_work;                          // slice ticket; self-resetting
__device__ unsigned int g_done;                          // block ticket; self-resetting

__device__ __forceinline__ float sl1(float pred, float target) {
    float a = fabsf(pred - target);
    float m = fminf(a, 1.0f);
    return m * (a - 0.5f * m);
}
__device__ __forceinline__ float sl1_acc(float acc, float d) {
    float a = fabsf(d);
    float m = fminf(a, 1.0f);
    return fmaf(m, fmaf(-0.5f, m, a), acc);
}

__device__ __forceinline__ unsigned int smem_u32(const void* p) {
    return (unsigned int)__cvta_generic_to_shared(p);
}
__device__ __forceinline__ void cpa4(unsigned int dst, const float* src) {
    asm volatile("cp.async.ca.shared.global [%0], [%1], 4;" :: "r"(dst), "l"(src));
}
#define CPC()  asm volatile("cp.async.commit_group;")
#define CPW(n) asm volatile("cp.async.wait_group %0;" :: "n"(n))

__global__ void __launch_bounds__(256, 4)
retrace_main(const float* __restrict__ q,
             const float* __restrict__ tq,
             const float* __restrict__ tv,
             const float* __restrict__ r,
             const float* __restrict__ olp,
             const float* __restrict__ tlp,
             float* __restrict__ out)
{
    const int tid  = threadIdx.x;
    const int lane = tid & 31;
    const int wrp  = tid >> 5;

    __shared__ float  s_liw[2][8 * RPAD];   // forward: tlp ; backward: q tile
    __shared__ float  s_r  [2][8 * RPAD];   // forward: r
    __shared__ float  s_tv [2][8 * RPAD];   // forward: tv
    __shared__ float  s_tq [2][8 * RPAD];   // forward: tq
    __shared__ float2 s_dp [8][DPROWS];     // per-column {decay, pd}, rows < DPROWS
    __shared__ int    s_nch[8];
    __shared__ double shw[8];
    __shared__ int    s_v;

    auto block_reduce = [&](double val) -> double {   // deterministic fixed order
        #pragma unroll
        for (int off = 16; off > 0; off >>= 1)
            val += __shfl_xor_sync(FULLM, val, off);
        __syncthreads();
        if (lane == 0) shw[wrp] = val;
        __syncthreads();
        double s = 0.0;
        #pragma unroll
        for (int i = 0; i < 8; ++i) s += shw[i];
        return s;
    };

    if (blockIdx.x < SCAN_BLOCKS) {
        // ===== one WARP per column; 64-row rounds staged via cp.async, 2-deep =====
        const int k0 = blockIdx.x * 8;
        const int k  = k0 + wrp;
        double acc = 0.0;

        float carry = 0.0f;
        int   tstop = TM1;
        bool  warp_dead = false;

        auto stage_f = [&](int buf, int rnd) {
            #pragma unroll
            for (int i = 0; i < 2; ++i) {
                const int idx = tid + 256 * i;
                const int row = idx >> 3, col = idx & 7;
                const int tc  = min(rnd * 64 + row, TM1 - 1);
                const unsigned int d = (unsigned int)(col * RPAD + row) * 4u;
                cpa4(smem_u32(&s_liw[buf][0]) + d, tlp + (size_t)(tc + 1) * K_DIM + k0 + col);
                cpa4(smem_u32(&s_r  [buf][0]) + d, r   + (size_t)tc       * K_DIM + k0 + col);
                cpa4(smem_u32(&s_tv [buf][0]) + d, tv  + (size_t)(tc + 1) * K_DIM + k0 + col);
                cpa4(smem_u32(&s_tq [buf][0]) + d, tq  + (size_t)(tc + 1) * K_DIM + k0 + col);
            }
        };
        auto comp_sub = [&](int buf, int rnd, int s) {
            const int  sc = rnd * 2 + s;
            const int  t  = sc * 32 + lane;
            const bool v  = t < TM1;
            const int  ro = s * 32 + lane;
            float liw = s_liw[buf][wrp * RPAD + ro] - (v ? olp[t + 1] : 0.0f);
            float m   = fminf(liw, 0.0f);
            float iw  = expf(m);
            float sv  = v ? (LOGG + m) : 0.0f;
            #pragma unroll
            for (int off = 1; off < 32; off <<= 1) {     // inclusive prefix sum
                float u = __shfl_up_sync(FULLM, sv, off);
                if (lane >= off) sv += u;
            }
            float ls    = carry + sv;
            float decay = expf(ls);                       // underflows to exact 0
            float pdv   = (s_r[buf][wrp * RPAD + ro]
                           + GAMMA * (s_tv[buf][wrp * RPAD + ro]
                                      - iw * s_tq[buf][wrp * RPAD + ro])) * decay;
            if (v) {
                if (t < DPROWS) s_dp[wrp][t] = make_float2(decay, pdv);
                else            g_dp[(size_t)k * TM1 + t] = make_float2(decay, pdv);
            }
            carry = __shfl_sync(FULLM, ls, 31);
            unsigned bal = __ballot_sync(FULLM, v && decay == 0.0f);
            if (bal && !warp_dead) { tstop = sc * 32 + (__ffs(bal) - 1); warp_dead = true; }
        };

        stage_f(0, 0); CPC();
        stage_f(1, 1); CPC();
        int rnd = 0;
        while (true) {
            CPW(1);
            __syncthreads();
            const int buf = rnd & 1;
            if (!warp_dead) comp_sub(buf, rnd, 0);
            if (!warp_dead) comp_sub(buf, rnd, 1);
            const bool allstop = __syncthreads_and(warp_dead) != 0;
            if (allstop || rnd + 1 >= NRND) break;
            if (rnd + 2 < NRND) stage_f(buf, rnd + 2);
            CPC();
            ++rnd;
        }

        const int nch = (tstop + 31) >> 5;
        if (lane == 0) s_nch[wrp] = nch;
        __syncthreads();
        int bmax = s_nch[0];
        #pragma unroll
        for (int i = 1; i < 8; ++i) bmax = max(bmax, s_nch[i]);
        const int rmax = (bmax + 1) >> 1;

        // ---- backward: q tiles staged via cp.async; dp from smem (global rare) ----
        auto stage_b = [&](int buf, int rr) {
            #pragma unroll
            for (int i = 0; i < 2; ++i) {
                const int idx = tid + 256 * i;
                const int row = idx >> 3, col = idx & 7;
                const int tc  = min(rr * 64 + row, TM1 - 1);
                cpa4(smem_u32(&s_liw[buf][0]) + (unsigned int)(col * RPAD + row) * 4u,
                     q + (size_t)tc * K_DIM + k0 + col);
            }
        };

        CPW(0);
        __syncthreads();
        float Rcarry = 0.0f;
        stage_b((rmax - 1) & 1, rmax - 1); CPC();
        for (int rr = rmax - 1; ; --rr) {
            if (rr > 0) { stage_b((rr - 1) & 1, rr - 1); CPC(); CPW(1); }
            else        { CPW(0); }
            __syncthreads();
            const int buf = rr & 1;
            #pragma unroll
            for (int s2 = 1; s2 >= 0; --s2) {
                const int  sc  = 2 * rr + s2;
                const int  t   = sc * 32 + lane;
                const bool act = (sc < nch) && (t < TM1);   // rows with meaningful dp
                // dp: smem for sc < DPSUB (always written there when active);
                // masked to exact 0 beyond nch (matches global zero-init semantics).
                float2 dp = make_float2(0.0f, 0.0f);
                if (act) dp = (sc < DPSUB) ? s_dp[wrp][t]
                                           : g_dp[(size_t)k * TM1 + t];
                float s = dp.y;
                #pragma unroll
                for (int off = 1; off < 32; off <<= 1) {    // inclusive suffix sum
                    float u = __shfl_down_sync(FULLM, s, off);
                    if (lane + off < 32) s += u;
                }
                float R    = s + Rcarry;
                float retr = R / fmaxf(dp.x, 1e-10f);
                float qv   = s_liw[buf][wrp * RPAD + s2 * 32 + lane];
                if (act) acc += (double)(sl1(qv, retr) - sl1(qv, 0.0f));
                Rcarry = __shfl_sync(FULLM, R, 0);
            }
            if (rr == 0) break;
            __syncthreads();
        }

        double bsum = block_reduce(acc);
        if (tid == 0) g_part[NSLICE + blockIdx.x] = bsum;
    }

    // ===== dynamic work-stealing over 512 x 128KB slices, 8 loads in flight =====
    // g_part[v] is slice-indexed -> value and finalize order deterministic
    // regardless of which block computes which slice.
    const float4* q4 = (const float4*)q;
    while (true) {
        if (tid == 0) s_v = (int)atomicAdd(&g_work, 1u);
        __syncthreads();
        const int v = s_v;
        if (v >= NSLICE) break;

        const long long base = (long long)v * 8192 + tid;   // 8192 float4 per slice
        float f0 = 0.0f, f1 = 0.0f, f2 = 0.0f, f3 = 0.0f;
        #pragma unroll
        for (int h = 0; h < 4; ++h) {                 // 4 batches x 8 float4/thread
            float4 x[8];
            #pragma unroll
            for (int j = 0; j < 8; ++j) {             // 8 independent loads in flight
                const long long i = base + (long long)h * 2048 + j * 256;
                x[j] = (i < NVEC) ? q4[i] : make_float4(0.f, 0.f, 0.f, 0.f);
            }
            #pragma unroll
            for (int j = 0; j < 8; ++j) {
                float4 a = x[j];
                float* f = (j & 2) ? ((j & 1) ? &f3 : &f2) : ((j & 1) ? &f1 : &f0);
                *f = sl1_acc(sl1_acc(sl1_acc(sl1_acc(*f, a.x), a.y), a.z), a.w);
            }
        }
        double ssum = block_reduce((double)((f0 + f1) + (f2 + f3)));
        if (tid == 0) g_part[v] = ssum;
        __syncthreads();                     // protect s_v / shw for next iteration
    }

    // ---- fused last-block finalize (deterministic fixed-order final sum) ----
    __shared__ unsigned int sticket;
    if (tid == 0) {
        __threadfence();
        sticket = atomicAdd(&g_done, 1u);
    }
    __syncthreads();
    if (sticket == NBLOCKS - 1) {
        __threadfence();
        double a = 0.0;
        for (int i = tid; i < NPART; i += 256) a += g_part[i];
        __shared__ double sh[256];
        sh[tid] = a;
        __syncthreads();
        #pragma unroll
        for (int s = 128; s > 0; s >>= 1) {
            if (tid < s) sh[tid] += sh[tid + s];
            __syncthreads();
        }
        if (tid == 0) {
            out[0] = (float)(sh[0] / (double)NTOT);
            g_work = 0;                      // reset tickets for next graph replay
            g_done = 0;
        }
    }
}

extern "C" void kernel_launch(void* const* d_in, const int* in_sizes, int n_in,
                              void* d_out, int out_size)
{
    const float* q   = (const float*)d_in[0];  // state_trajectory_action_values (T,K)
    const float* tq  = (const float*)d_in[1];  // target_state_trajectory_action_values (T,K)
    const float* tv  = (const float*)d_in[2];  // target_expected_state_values (T,K)
    const float* r   = (const float*)d_in[3];  // rewards (T,K)
    const float* olp = (const float*)d_in[4];  // original_log_trajectory_action_probs (T,)
    const float* tlp = (const float*)d_in[5];  // target_log_trajectory_task_action_probs (T,K)
    float* out = (float*)d_out;

    retrace_main<<<NBLOCKS, 256>>>(q, tq, tv, r, olp, tlp, out);
}

// round 17
// speedup vs baseline: 1.2166x; 1.0069x over previous
#include <cuda_runtime.h>
#include <cuda_bf16.h>
#include <cstdint>

#define T_DIM 8192
#define K_DIM 2048
#define TM1   (T_DIM - 1)                      // 8191 rows in the loss
#define NTOT  ((long long)TM1 * K_DIM)         // 16,775,168 elements
#define NVEC  (NTOT / 4)                       // 4,193,792 float4
#define GAMMA 0.99f
#define LOGG  (-0.0100503358535014f)           // logf(0.99)

#define SCAN_BLOCKS  256                       // FIRST block IDs -> spread over all SMs
#define NBLOCKS      592                       // 4 blocks/SM * 148 SMs (one wave)
#define NSLICE       512                       // 512 slices x 8192 float4 (128 KB each)
#define NPART        (NSLICE + SCAN_BLOCKS)
#define FULLM        0xFFFFFFFFu

#define RPAD     68                            // rows-per-col stride (64+4): conflict-free
#define NRND     128                           // 128 rounds x 64 rows >= TM1
#define DPROWS   320                           // smem-resident dp/q rows (10 sub-chunks)
#define DPSUB    (DPROWS / 32)                 // 10
#define QSTRIDE  324                           // q-tile stride: (324c+r)%32 = (4c+r)%32

// Scratch (device globals are the allowed scratch mechanism).
// g_dp is the rare-case spill for columns surviving >= DPROWS rows (zero-init).
__device__ float2       g_dp  [(long long)K_DIM * TM1];  // {decay, td*decay}, [k][t]
__device__ double       g_part[NPART];
__device__ unsigned int g_work;                          // slice ticket; self-resetting
__device__ unsigned int g_done;                          // block ticket; self-resetting

__device__ __forceinline__ float sl1(float pred, float target) {
    float a = fabsf(pred - target);
    float m = fminf(a, 1.0f);
    return m * (a - 0.5f * m);
}
__device__ __forceinline__ float sl1_acc(float acc, float d) {
    float a = fabsf(d);
    float m = fminf(a, 1.0f);
    return fmaf(m, fmaf(-0.5f, m, a), acc);
}

__device__ __forceinline__ unsigned int smem_u32(const void* p) {
    return (unsigned int)__cvta_generic_to_shared(p);
}
__device__ __forceinline__ void cpa4(unsigned int dst, const float* src) {
    asm volatile("cp.async.ca.shared.global [%0], [%1], 4;" :: "r"(dst), "l"(src));
}
#define CPC()  asm volatile("cp.async.commit_group;")
#define CPW(n) asm volatile("cp.async.wait_group %0;" :: "n"(n))

__global__ void __launch_bounds__(256, 4)
retrace_main(const float* __restrict__ q,
             const float* __restrict__ tq,
             const float* __restrict__ tv,
             const float* __restrict__ r,
             const float* __restrict__ olp,
             const float* __restrict__ tlp,
             float* __restrict__ out)
{
    const int tid  = threadIdx.x;
    const int lane = tid & 31;
    const int wrp  = tid >> 5;

    __shared__ float  s_liw[2][8 * RPAD];   // staged tlp
    __shared__ float  s_r  [2][8 * RPAD];   // staged r
    __shared__ float  s_tv [2][8 * RPAD];   // staged tv
    __shared__ float  s_tq [2][8 * RPAD];   // staged tq
    __shared__ float2 s_dp [8][DPROWS];     // per-column {decay, pd}, rows < DPROWS
    __shared__ float  s_q  [8][QSTRIDE];    // per-column q, rows < DPROWS (320 used)
    __shared__ double shw[8];
    __shared__ int    s_v;

    auto block_reduce = [&](double val) -> double {   // deterministic fixed order
        #pragma unroll
        for (int off = 16; off > 0; off >>= 1)
            val += __shfl_xor_sync(FULLM, val, off);
        __syncthreads();
        if (lane == 0) shw[wrp] = val;
        __syncthreads();
        double s = 0.0;
        #pragma unroll
        for (int i = 0; i < 8; ++i) s += shw[i];
        return s;
    };

    if (blockIdx.x < SCAN_BLOCKS) {
        // ===== one WARP per column; 64-row rounds staged via cp.async, 2-deep =====
        const int k0 = blockIdx.x * 8;
        const int k  = k0 + wrp;
        double acc = 0.0;

        float carry = 0.0f;
        int   tstop = TM1;
        bool  warp_dead = false;

        auto stage_f = [&](int buf, int rnd) {
            #pragma unroll
            for (int i = 0; i < 2; ++i) {
                const int idx = tid + 256 * i;
                const int row = idx >> 3, col = idx & 7;
                const int tc  = min(rnd * 64 + row, TM1 - 1);
                const unsigned int d = (unsigned int)(col * RPAD + row) * 4u;
                cpa4(smem_u32(&s_liw[buf][0]) + d, tlp + (size_t)(tc + 1) * K_DIM + k0 + col);
                cpa4(smem_u32(&s_r  [buf][0]) + d, r   + (size_t)tc       * K_DIM + k0 + col);
                cpa4(smem_u32(&s_tv [buf][0]) + d, tv  + (size_t)(tc + 1) * K_DIM + k0 + col);
                cpa4(smem_u32(&s_tq [buf][0]) + d, tq  + (size_t)(tc + 1) * K_DIM + k0 + col);
                if (rnd < DPROWS / 64)          // q rows < 320 for the backward pass
                    cpa4(smem_u32(&s_q[0][0])
                             + (unsigned int)(col * QSTRIDE + rnd * 64 + row) * 4u,
                         q + (size_t)tc * K_DIM + k0 + col);
            }
        };
        auto comp_sub = [&](int buf, int rnd, int s) {
            const int  sc = rnd * 2 + s;
            const int  t  = sc * 32 + lane;
            const bool v  = t < TM1;
            const int  ro = s * 32 + lane;
            float liw = s_liw[buf][wrp * RPAD + ro] - (v ? olp[t + 1] : 0.0f);
            float m   = fminf(liw, 0.0f);
            float iw  = expf(m);
            float sv  = v ? (LOGG + m) : 0.0f;
            #pragma unroll
            for (int off = 1; off < 32; off <<= 1) {     // inclusive prefix sum
                float u = __shfl_up_sync(FULLM, sv, off);
                if (lane >= off) sv += u;
            }
            float ls    = carry + sv;
            float decay = expf(ls);                       // underflows to exact 0
            float pdv   = (s_r[buf][wrp * RPAD + ro]
                           + GAMMA * (s_tv[buf][wrp * RPAD + ro]
                                      - iw * s_tq[buf][wrp * RPAD + ro])) * decay;
            if (v) {
                if (t < DPROWS) s_dp[wrp][t] = make_float2(decay, pdv);
                else            g_dp[(size_t)k * TM1 + t] = make_float2(decay, pdv);
            }
            carry = __shfl_sync(FULLM, ls, 31);
            unsigned bal = __ballot_sync(FULLM, v && decay == 0.0f);
            if (bal && !warp_dead) { tstop = sc * 32 + (__ffs(bal) - 1); warp_dead = true; }
        };

        stage_f(0, 0); CPC();
        stage_f(1, 1); CPC();
        int rnd = 0;
        while (true) {
            CPW(1);
            __syncthreads();
            const int buf = rnd & 1;
            if (!warp_dead) comp_sub(buf, rnd, 0);
            if (!warp_dead) comp_sub(buf, rnd, 1);
            const bool allstop = __syncthreads_and(warp_dead) != 0;
            if (allstop || rnd + 1 >= NRND) break;
            if (rnd + 2 < NRND) stage_f(buf, rnd + 2);
            CPC();
            ++rnd;
        }

        // join staging once: s_q rows were staged by sibling warps
        CPW(0);
        __syncthreads();

        // ---- backward: fully warp-local, zero barriers, smem-resident ----
        const int nch = (tstop + 31) >> 5;               // sub-chunks with live data
        float Rcarry = 0.0f;
        for (int sc = nch - 1; sc >= 0; --sc) {
            const int  t   = sc * 32 + lane;
            float dx, dy, qv;
            bool  act;
            if (sc < DPSUB) {                            // t < 320 < TM1: always active
                float2 dp = s_dp[wrp][t];
                dx = dp.x; dy = dp.y;
                qv = s_q[wrp][t];
                act = true;
            } else {                                     // rare spill path (t >= 320)
                act = t < TM1;
                dx = 0.0f; dy = 0.0f; qv = 0.0f;
                if (act) {
                    float2 dp = g_dp[(size_t)k * TM1 + t];
                    dx = dp.x; dy = dp.y;
                    qv = q[(size_t)t * K_DIM + k];
                }
            }
            float s = dy;
            #pragma unroll
            for (int off = 1; off < 32; off <<= 1) {     // inclusive suffix sum
                float u = __shfl_down_sync(FULLM, s, off);
                if (lane + off < 32) s += u;
            }
            float R    = s + Rcarry;
            float retr = R / fmaxf(dx, 1e-10f);
            if (act) acc += (double)(sl1(qv, retr) - sl1(qv, 0.0f));
            Rcarry = __shfl_sync(FULLM, R, 0);
        }

        double bsum = block_reduce(acc);
        if (tid == 0) g_part[NSLICE + blockIdx.x] = bsum;
    }

    // ===== dynamic work-stealing over 512 x 128KB slices, 8 loads in flight =====
    // g_part[v] is slice-indexed -> value and finalize order deterministic
    // regardless of which block computes which slice.
    const float4* q4 = (const float4*)q;
    while (true) {
        if (tid == 0) s_v = (int)atomicAdd(&g_work, 1u);
        __syncthreads();
        const int v = s_v;
        if (v >= NSLICE) break;

        const long long base = (long long)v * 8192 + tid;   // 8192 float4 per slice
        float f0 = 0.0f, f1 = 0.0f, f2 = 0.0f, f3 = 0.0f;
        #pragma unroll
        for (int h = 0; h < 4; ++h) {                 // 4 batches x 8 float4/thread
            float4 x[8];
            #pragma unroll
            for (int j = 0; j < 8; ++j) {             // 8 independent loads in flight
                const long long i = base + (long long)h * 2048 + j * 256;
                x[j] = (i < NVEC) ? q4[i] : make_float4(0.f, 0.f, 0.f, 0.f);
            }
            #pragma unroll
            for (int j = 0; j < 8; ++j) {
                float4 a = x[j];
                float* f = (j & 2) ? ((j & 1) ? &f3 : &f2) : ((j & 1) ? &f1 : &f0);
                *f = sl1_acc(sl1_acc(sl1_acc(sl1_acc(*f, a.x), a.y), a.z), a.w);
            }
        }
        double ssum = block_reduce((double)((f0 + f1) + (f2 + f3)));
        if (tid == 0) g_part[v] = ssum;
        __syncthreads();                     // protect s_v / shw for next iteration
    }

    // ---- fused last-block finalize (deterministic fixed-order final sum) ----
    __shared__ unsigned int sticket;
    if (tid == 0) {
        __threadfence();
        sticket = atomicAdd(&g_done, 1u);
    }
    __syncthreads();
    if (sticket == NBLOCKS - 1) {
        __threadfence();
        double a = 0.0;
        for (int i = tid; i < NPART; i += 256) a += g_part[i];
        // reuse the retired s_dp region as the finalize scratch (saves 2KB static)
        double* sh = reinterpret_cast<double*>(&s_dp[0][0]);
        sh[tid] = a;
        __syncthreads();
        #pragma unroll
        for (int s = 128; s > 0; s >>= 1) {
            if (tid < s) sh[tid] += sh[tid + s];
            __syncthreads();
        }
        if (tid == 0) {
            out[0] = (float)(sh[0] / (double)NTOT);
            g_work = 0;                      // reset tickets for next graph replay
            g_done = 0;
        }
    }
}

extern "C" void kernel_launch(void* const* d_in, const int* in_sizes, int n_in,
                              void* d_out, int out_size)
{
    const float* q   = (const float*)d_in[0];  // state_trajectory_action_values (T,K)
    const float* tq  = (const float*)d_in[1];  // target_state_trajectory_action_values (T,K)
    const float* tv  = (const float*)d_in[2];  // target_expected_state_values (T,K)
    const float* r   = (const float*)d_in[3];  // rewards (T,K)
    const float* olp = (const float*)d_in[4];  // original_log_trajectory_action_probs (T,)
    const float* tlp = (const float*)d_in[5];  // target_log_trajectory_task_action_probs (T,K)
    float* out = (float*)d_out;

    retrace_main<<<NBLOCKS, 256>>>(q, tq, tv, r, olp, tlp, out);
}